// round 4
// baseline (speedup 1.0000x reference)
#include <cuda_runtime.h>
#include <math.h>

#define NN 50000
#define EE 800000
#define HID 128

// ---------------- scratch (device globals; no allocations allowed) ----------
__device__ __align__(16) float    g_xl[NN * HID];      // x @ Wl + bl
__device__ __align__(16) float    g_xr[NN * HID];      // x @ Wr + br
__device__ __align__(16) float    g_accum[NN * HID];   // scatter-sum output
__device__ __align__(16) float    g_logits[EE * 4];    // per-edge logits, then exp()
__device__ float                  g_den[NN * 4];       // softmax denominators
__device__ unsigned               g_lmax[NN * 4];      // order-preserving max keys

// order-preserving float<->uint encoding for atomicMax
__device__ __forceinline__ unsigned enc_f(float x) {
    unsigned b = __float_as_uint(x);
    return (b & 0x80000000u) ? ~b : (b | 0x80000000u);
}
__device__ __forceinline__ float dec_f(unsigned k) {
    unsigned b = (k & 0x80000000u) ? (k ^ 0x80000000u) : ~k;
    return __uint_as_float(b);
}

// ---------------- k0: zero scratch --------------------------------------
__global__ void k0_init() {
    int t = blockIdx.x * blockDim.x + threadIdx.x;
    if (t < NN * HID) g_accum[t] = 0.f;
    if (t < NN * 4) { g_den[t] = 0.f; g_lmax[t] = 0u; }
}

// ---------------- k1: xl = x@Wl+bl, xr = x@Wr+br -------------------------
// block: 128 threads (one per output column), 16 rows per block
__global__ void k1_linear(const float* __restrict__ x,
                          const float* __restrict__ Wl, const float* __restrict__ bl,
                          const float* __restrict__ Wr, const float* __restrict__ br) {
    __shared__ __align__(16) float xs[16][HID];
    int j = threadIdx.x;
    int row0 = blockIdx.x * 16;
#pragma unroll
    for (int r = 0; r < 16; r++) {
        int rr = row0 + r;
        xs[r][j] = (rr < NN) ? x[rr * HID + j] : 0.f;
    }
    __syncthreads();
    float accl[16], accr[16];
#pragma unroll
    for (int r = 0; r < 16; r++) { accl[r] = 0.f; accr[r] = 0.f; }
    for (int k = 0; k < HID; k++) {
        float wl = Wl[k * HID + j];
        float wr = Wr[k * HID + j];
#pragma unroll
        for (int r = 0; r < 16; r++) {
            float xv = xs[r][k];
            accl[r] = fmaf(xv, wl, accl[r]);
            accr[r] = fmaf(xv, wr, accr[r]);
        }
    }
    float blv = bl[j], brv = br[j];
#pragma unroll
    for (int r = 0; r < 16; r++) {
        int rr = row0 + r;
        if (rr < NN) {
            g_xl[rr * HID + j] = accl[r] + blv;
            g_xr[rr * HID + j] = accr[r] + brv;
        }
    }
}

// ---------------- k2: per-edge logits + segment max ----------------------
// one warp per edge; lane owns channels c = 4*lane .. 4*lane+3 (head = lane/8)
__global__ void k2_logits(const int* __restrict__ ei, const float* __restrict__ ea,
                          const float* __restrict__ We, const float* __restrict__ att) {
    __shared__ __align__(16) float sWe[16 * HID];
    for (int i = threadIdx.x; i < 16 * HID; i += blockDim.x) sWe[i] = We[i];
    __syncthreads();

    int e = (blockIdx.x * blockDim.x + threadIdx.x) >> 5;
    int lane = threadIdx.x & 31;
    if (e >= EE) return;

    int src = ei[e];
    int dst = ei[EE + e];
    float4 xl = ((const float4*)g_xl)[src * 32 + lane];
    float4 xr = ((const float4*)g_xr)[dst * 32 + lane];
    float4 m = make_float4(xl.x + xr.x, xl.y + xr.y, xl.z + xr.z, xl.w + xr.w);

    const float* eap = ea + (size_t)e * 16;
#pragma unroll
    for (int k = 0; k < 16; k++) {
        float a = __ldg(eap + k);
        float4 w = ((const float4*)sWe)[k * 32 + lane];
        m.x = fmaf(a, w.x, m.x);
        m.y = fmaf(a, w.y, m.y);
        m.z = fmaf(a, w.z, m.z);
        m.w = fmaf(a, w.w, m.w);
    }
    // LeakyReLU(0.2)
    float4 s;
    s.x = m.x > 0.f ? m.x : 0.2f * m.x;
    s.y = m.y > 0.f ? m.y : 0.2f * m.y;
    s.z = m.z > 0.f ? m.z : 0.2f * m.z;
    s.w = m.w > 0.f ? m.w : 0.2f * m.w;

    // att flattened over (h, c) == per-channel weight: index = c
    float4 av = ((const float4*)att)[lane];
    float p = s.x * av.x + s.y * av.y + s.z * av.z + s.w * av.w;
    // reduce within each 8-lane (per-head) group
    p += __shfl_xor_sync(0xffffffffu, p, 1);
    p += __shfl_xor_sync(0xffffffffu, p, 2);
    p += __shfl_xor_sync(0xffffffffu, p, 4);
    if ((lane & 7) == 0) {
        int h = lane >> 3;
        g_logits[e * 4 + h] = p;
        atomicMax(&g_lmax[dst * 4 + h], enc_f(p));
    }
}

// ---------------- k3: exp(logit - max) + denominator ----------------------
__global__ void k3_softmax(const int* __restrict__ ei) {
    int t = blockIdx.x * blockDim.x + threadIdx.x;
    if (t >= EE * 4) return;
    int e = t >> 2, h = t & 3;
    int dst = ei[EE + e];
    float L = g_logits[t];
    float mx = dec_f(g_lmax[dst * 4 + h]);
    float ex = expf(L - mx);
    g_logits[t] = ex;   // in-place: same thread read this slot
    atomicAdd(&g_den[dst * 4 + h], ex);
}

// ---------------- k4: weighted scatter-sum of xl[src] ---------------------
// one warp per edge; vector reductions (red.v4) into g_accum[dst]
__global__ void k4_scatter(const int* __restrict__ ei) {
    int e = (blockIdx.x * blockDim.x + threadIdx.x) >> 5;
    int lane = threadIdx.x & 31;
    if (e >= EE) return;
    int src = ei[e];
    int dst = ei[EE + e];
    int h = lane >> 3;
    float ex = g_logits[e * 4 + h];
    float den = g_den[dst * 4 + h];
    float alpha = ex / (den + 1e-16f);
    float4 v = ((const float4*)g_xl)[src * 32 + lane];
    v.x *= alpha; v.y *= alpha; v.z *= alpha; v.w *= alpha;
    float* p = g_accum + (size_t)dst * HID + lane * 4;
    asm volatile("red.global.add.v4.f32 [%0], {%1, %2, %3, %4};"
                 :: "l"(p), "f"(v.x), "f"(v.y), "f"(v.z), "f"(v.w)
                 : "memory");
}

// ---------------- k5: fused RMSNorm -> FFN(GELU) -> RMSNorm ---------------
// block: 256 threads, 16 rows
__global__ void __launch_bounds__(256)
k5_ffn(const float* __restrict__ x, const float* __restrict__ bias_gat,
       const float* __restrict__ wn1,
       const float* __restrict__ W1, const float* __restrict__ b1,
       const float* __restrict__ W2, const float* __restrict__ b2,
       const float* __restrict__ wn2, float* __restrict__ out) {
    __shared__ __align__(16) float hs[16][HID];
    __shared__ __align__(16) float gs[16][512];
    const float EPS = 1.1920929e-07f;   // finfo(float32).eps
    int tid = threadIdx.x;
    int warp = tid >> 5, lane = tid & 31;
    int row0 = blockIdx.x * 16;

    // phase 0: h = rmsnorm(x + accum + bias_gat, wn1); warp handles 2 rows
#pragma unroll
    for (int rr = 0; rr < 2; rr++) {
        int r = warp * 2 + rr;
        int node = row0 + r;
        float4 v = make_float4(0.f, 0.f, 0.f, 0.f);
        if (node < NN) {
            float4 xv = ((const float4*)x)[node * 32 + lane];
            float4 a  = ((const float4*)g_accum)[node * 32 + lane];
            float4 bg = ((const float4*)bias_gat)[lane];
            v = make_float4(xv.x + a.x + bg.x, xv.y + a.y + bg.y,
                            xv.z + a.z + bg.z, xv.w + a.w + bg.w);
        }
        float ss = v.x * v.x + v.y * v.y + v.z * v.z + v.w * v.w;
#pragma unroll
        for (int o = 16; o > 0; o >>= 1) ss += __shfl_xor_sync(0xffffffffu, ss, o);
        float rs = rsqrtf(ss * (1.f / 128.f) + EPS);
        float4 w = ((const float4*)wn1)[lane];
        float4 hv = make_float4(v.x * rs * w.x, v.y * rs * w.y,
                                v.z * rs * w.z, v.w * rs * w.w);
        ((float4*)&hs[r][0])[lane] = hv;
    }
    __syncthreads();

    // phase 1: hidden = gelu(h @ W1 + b1); thread owns cols tid, tid+256
    float acc0[16], acc1[16];
#pragma unroll
    for (int r = 0; r < 16; r++) { acc0[r] = 0.f; acc1[r] = 0.f; }
    for (int k = 0; k < HID; k++) {
        float wa = W1[k * 512 + tid];
        float wb = W1[k * 512 + tid + 256];
#pragma unroll
        for (int r = 0; r < 16; r++) {
            float hk = hs[r][k];
            acc0[r] = fmaf(hk, wa, acc0[r]);
            acc1[r] = fmaf(hk, wb, acc1[r]);
        }
    }
    {
        float ba = b1[tid], bb = b1[tid + 256];
        const float ISQRT2 = 0.70710678118654752f;
#pragma unroll
        for (int r = 0; r < 16; r++) {
            float u = acc0[r] + ba;
            gs[r][tid] = 0.5f * u * (1.f + erff(u * ISQRT2));
            float u2 = acc1[r] + bb;
            gs[r][tid + 256] = 0.5f * u2 * (1.f + erff(u2 * ISQRT2));
        }
    }
    __syncthreads();

    // phase 2: f = hidden @ W2 + b2; thread owns cols c0,c0+64 for 4 rows
    int c0 = tid & 63;
    int rg = tid >> 6;          // 0..3 -> rows rg*4 .. rg*4+3
    float a0[4] = {0.f, 0.f, 0.f, 0.f};
    float a1[4] = {0.f, 0.f, 0.f, 0.f};
    for (int k = 0; k < 512; k++) {
        float w0 = W2[k * HID + c0];
        float w1v = W2[k * HID + c0 + 64];
#pragma unroll
        for (int r = 0; r < 4; r++) {
            float g = gs[rg * 4 + r][k];
            a0[r] = fmaf(g, w0, a0[r]);
            a1[r] = fmaf(g, w1v, a1[r]);
        }
    }
    __syncthreads();            // all reads of gs done
    {
        float b2a = b2[c0], b2b = b2[c0 + 64];
        float* fs = &gs[0][0];  // reuse gs as [16][128] f buffer
#pragma unroll
        for (int r = 0; r < 4; r++) {
            fs[(rg * 4 + r) * HID + c0]      = a0[r] + b2a;
            fs[(rg * 4 + r) * HID + c0 + 64] = a1[r] + b2b;
        }
    }
    __syncthreads();

    // phase 3: out = rmsnorm(h + f, wn2)
    float* fs = &gs[0][0];
#pragma unroll
    for (int rr = 0; rr < 2; rr++) {
        int r = warp * 2 + rr;
        int node = row0 + r;
        float4 hv = ((const float4*)&hs[r][0])[lane];
        float4 fv = ((const float4*)fs)[r * 32 + lane];
        float4 z = make_float4(hv.x + fv.x, hv.y + fv.y, hv.z + fv.z, hv.w + fv.w);
        float ss = z.x * z.x + z.y * z.y + z.z * z.z + z.w * z.w;
#pragma unroll
        for (int o = 16; o > 0; o >>= 1) ss += __shfl_xor_sync(0xffffffffu, ss, o);
        float rs = rsqrtf(ss * (1.f / 128.f) + EPS);
        float4 w = ((const float4*)wn2)[lane];
        if (node < NN) {
            ((float4*)out)[node * 32 + lane] =
                make_float4(z.x * rs * w.x, z.y * rs * w.y,
                            z.z * rs * w.z, z.w * rs * w.w);
        }
    }
}

// ---------------- launch ---------------------------------------------------
extern "C" void kernel_launch(void* const* d_in, const int* in_sizes, int n_in,
                              void* d_out, int out_size) {
    const float* x        = (const float*)d_in[0];
    const int*   ei       = (const int*)  d_in[1];
    const float* ea       = (const float*)d_in[2];
    const float* Wl       = (const float*)d_in[3];
    const float* bl       = (const float*)d_in[4];
    const float* Wr       = (const float*)d_in[5];
    const float* br       = (const float*)d_in[6];
    const float* We       = (const float*)d_in[7];
    const float* att      = (const float*)d_in[8];
    const float* bias_gat = (const float*)d_in[9];
    const float* wn1      = (const float*)d_in[10];
    const float* wn2      = (const float*)d_in[11];
    const float* W1       = (const float*)d_in[12];
    const float* b1       = (const float*)d_in[13];
    const float* W2       = (const float*)d_in[14];
    const float* b2       = (const float*)d_in[15];
    float* out = (float*)d_out;

    k0_init<<<(NN * HID + 255) / 256, 256>>>();
    k1_linear<<<(NN + 15) / 16, 128>>>(x, Wl, bl, Wr, br);
    k2_logits<<<EE / 8, 256>>>(ei, ea, We, att);
    k3_softmax<<<(EE * 4) / 256, 256>>>(ei);
    k4_scatter<<<EE / 8, 256>>>(ei);
    k5_ffn<<<(NN + 15) / 16, 256>>>(x, bias_gat, wn1, W1, b1, W2, b2, wn2, out);
}

// round 6
// speedup vs baseline: 1.1887x; 1.1887x over previous
#include <cuda_runtime.h>
#include <math.h>

#define NN 50000
#define EE 800000
#define HID 128
#define SROW 132   // padded smem row stride (floats): conflict-free fragment loads

// ---------------- scratch (device globals; no allocations allowed) ----------
__device__ __align__(16) float    g_xl[NN * HID];      // x @ Wl + bl
__device__ __align__(16) float    g_xr[NN * HID];      // x @ Wr + br
__device__ __align__(16) float    g_accum[NN * HID];   // scatter-sum output
__device__ __align__(16) float    g_logits[EE * 4];    // per-edge logits, then exp()
__device__ float                  g_den[NN * 4];       // softmax denominators
__device__ unsigned               g_lmax[NN * 4];      // order-preserving max keys

// order-preserving float<->uint encoding for atomicMax
__device__ __forceinline__ unsigned enc_f(float x) {
    unsigned b = __float_as_uint(x);
    return (b & 0x80000000u) ? ~b : (b | 0x80000000u);
}
__device__ __forceinline__ float dec_f(unsigned k) {
    unsigned b = (k & 0x80000000u) ? (k ^ 0x80000000u) : ~k;
    return __uint_as_float(b);
}

// round fp32 -> tf32 (rna), returned as fp32 bit pattern
__device__ __forceinline__ float tf32r(float x) {
    unsigned r;
    asm("cvt.rna.tf32.f32 %0, %1;" : "=r"(r) : "f"(x));
    return __uint_as_float(r);
}

// k-index permutation inside each 8-group: logical (c, c+4) become adjacent,
// so A/B fragment pairs load as one LDS.64
__device__ __forceinline__ int permk(int k) {
    return (k & ~7) | ((k & 3) << 1) | ((k >> 2) & 1);
}

// m16n8k8 tf32 mma, C += A*B
__device__ __forceinline__ void mma8(float* c, const unsigned* a, const unsigned* b) {
    asm volatile(
        "mma.sync.aligned.m16n8k8.row.col.f32.tf32.tf32.f32 "
        "{%0,%1,%2,%3}, {%4,%5,%6,%7}, {%8,%9}, {%0,%1,%2,%3};"
        : "+f"(c[0]), "+f"(c[1]), "+f"(c[2]), "+f"(c[3])
        : "r"(a[0]), "r"(a[1]), "r"(a[2]), "r"(a[3]), "r"(b[0]), "r"(b[1]));
}

// Warp tile M64 x N32 GEMM over K=128 from smem (tf32-prerounded, k-permuted).
// pA/pB already offset by lc2 = 2*(lane%4). Accumulates into c[4][4][4].
__device__ __forceinline__ void warp_gemm(const float* pA, const float* pB,
                                          float c[4][4][4]) {
#pragma unroll
    for (int ks = 0; ks < 16; ks++) {
        int kb = ks * 8;
        unsigned a[4][4], b[4][2];
#pragma unroll
        for (int mt = 0; mt < 4; mt++) {
            float2 t0 = *(const float2*)(pA + (mt * 16) * SROW + kb);
            float2 t1 = *(const float2*)(pA + (mt * 16 + 8) * SROW + kb);
            a[mt][0] = __float_as_uint(t0.x); a[mt][2] = __float_as_uint(t0.y);
            a[mt][1] = __float_as_uint(t1.x); a[mt][3] = __float_as_uint(t1.y);
        }
#pragma unroll
        for (int nt = 0; nt < 4; nt++) {
            float2 t = *(const float2*)(pB + (nt * 8) * SROW + kb);
            b[nt][0] = __float_as_uint(t.x); b[nt][1] = __float_as_uint(t.y);
        }
#pragma unroll
        for (int mt = 0; mt < 4; mt++)
#pragma unroll
            for (int nt = 0; nt < 4; nt++)
                mma8(c[mt][nt], a[mt], b[nt]);
    }
}

// ---------------- k0: zero scratch --------------------------------------
__global__ void k0_init() {
    int t = blockIdx.x * blockDim.x + threadIdx.x;
    if (t < NN * HID) g_accum[t] = 0.f;
    if (t < NN * 4) { g_den[t] = 0.f; g_lmax[t] = 0u; }
}

// ---------------- k1: xl = x@Wl+bl, xr = x@Wr+br via tf32 mma -------------
__global__ void __launch_bounds__(256)
k1_mma(const float* __restrict__ x,
       const float* __restrict__ Wl, const float* __restrict__ bl,
       const float* __restrict__ Wr, const float* __restrict__ br) {
    extern __shared__ float sm[];
    float* xs = sm;                 // [128][SROW]
    float* wb = sm + 128 * SROW;    // [128][SROW]
    int tid = threadIdx.x, warp = tid >> 5, lane = tid & 31;
    int wm = warp >> 2, wn = warp & 3;
    int lr = lane >> 2, lc2 = (lane & 3) << 1;
    int row0 = blockIdx.x * 128;

    // stage x rows (tf32, k-permuted)
    for (int r = 0; r < 16; r++) {
        int row = warp * 16 + r, node = row0 + row;
        float4 v = make_float4(0.f, 0.f, 0.f, 0.f);
        if (node < NN) v = ((const float4*)x)[node * 32 + lane];
        int c0 = lane * 4;
        xs[row * SROW + permk(c0)]     = tf32r(v.x);
        xs[row * SROW + permk(c0 + 1)] = tf32r(v.y);
        xs[row * SROW + permk(c0 + 2)] = tf32r(v.z);
        xs[row * SROW + permk(c0 + 3)] = tf32r(v.w);
    }

    for (int half = 0; half < 2; half++) {
        const float* W    = half ? Wr : Wl;
        const float* bias = half ? br : bl;
        float* dst        = half ? g_xr : g_xl;
        __syncthreads();            // xs ready / prev-half reads of wb done
        for (int idx = tid; idx < 128 * 32; idx += 256) {
            int k = idx >> 5, n4 = (idx & 31) << 2;
            float4 w = *(const float4*)(W + k * HID + n4);
            int kp = permk(k);
            wb[(n4 + 0) * SROW + kp] = tf32r(w.x);
            wb[(n4 + 1) * SROW + kp] = tf32r(w.y);
            wb[(n4 + 2) * SROW + kp] = tf32r(w.z);
            wb[(n4 + 3) * SROW + kp] = tf32r(w.w);
        }
        __syncthreads();

        float c[4][4][4];
#pragma unroll
        for (int i = 0; i < 4; i++)
#pragma unroll
            for (int j = 0; j < 4; j++)
#pragma unroll
                for (int e = 0; e < 4; e++) c[i][j][e] = 0.f;

        warp_gemm(xs + (wm * 64 + lr) * SROW + lc2,
                  wb + (wn * 32 + lr) * SROW + lc2, c);

#pragma unroll
        for (int nt = 0; nt < 4; nt++) {
            int col = wn * 32 + nt * 8 + lc2;
            float b0 = bias[col], b1v = bias[col + 1];
#pragma unroll
            for (int mt = 0; mt < 4; mt++)
#pragma unroll
                for (int h = 0; h < 2; h++) {
                    int node = row0 + wm * 64 + mt * 16 + lr + h * 8;
                    if (node < NN) {
                        float2 o;
                        o.x = c[mt][nt][h * 2] + b0;
                        o.y = c[mt][nt][h * 2 + 1] + b1v;
                        *(float2*)(dst + (size_t)node * HID + col) = o;
                    }
                }
        }
    }
}

// ---------------- k2: per-edge logits + segment max ----------------------
__global__ void k2_logits(const int* __restrict__ ei, const float* __restrict__ ea,
                          const float* __restrict__ We, const float* __restrict__ att) {
    __shared__ __align__(16) float sWe[16 * HID];
    for (int i = threadIdx.x; i < 16 * HID; i += blockDim.x) sWe[i] = We[i];
    __syncthreads();

    int e = (blockIdx.x * blockDim.x + threadIdx.x) >> 5;
    int lane = threadIdx.x & 31;
    if (e >= EE) return;

    int src = ei[e];
    int dst = ei[EE + e];
    float4 xl = ((const float4*)g_xl)[src * 32 + lane];
    float4 xr = ((const float4*)g_xr)[dst * 32 + lane];
    float4 m = make_float4(xl.x + xr.x, xl.y + xr.y, xl.z + xr.z, xl.w + xr.w);

    const float* eap = ea + (size_t)e * 16;
#pragma unroll
    for (int k = 0; k < 16; k++) {
        float a = __ldg(eap + k);
        float4 w = ((const float4*)sWe)[k * 32 + lane];
        m.x = fmaf(a, w.x, m.x);
        m.y = fmaf(a, w.y, m.y);
        m.z = fmaf(a, w.z, m.z);
        m.w = fmaf(a, w.w, m.w);
    }
    float4 s;
    s.x = m.x > 0.f ? m.x : 0.2f * m.x;
    s.y = m.y > 0.f ? m.y : 0.2f * m.y;
    s.z = m.z > 0.f ? m.z : 0.2f * m.z;
    s.w = m.w > 0.f ? m.w : 0.2f * m.w;

    float4 av = ((const float4*)att)[lane];
    float p = s.x * av.x + s.y * av.y + s.z * av.z + s.w * av.w;
    p += __shfl_xor_sync(0xffffffffu, p, 1);
    p += __shfl_xor_sync(0xffffffffu, p, 2);
    p += __shfl_xor_sync(0xffffffffu, p, 4);
    if ((lane & 7) == 0) {
        int h = lane >> 3;
        g_logits[e * 4 + h] = p;
        atomicMax(&g_lmax[dst * 4 + h], enc_f(p));
    }
}

// ---------------- k3: exp(logit - max) + denominator ----------------------
__global__ void k3_softmax(const int* __restrict__ ei) {
    int t = blockIdx.x * blockDim.x + threadIdx.x;
    if (t >= EE * 4) return;
    int e = t >> 2, h = t & 3;
    int dst = ei[EE + e];
    float L = g_logits[t];
    float mx = dec_f(g_lmax[dst * 4 + h]);
    float ex = expf(L - mx);
    g_logits[t] = ex;
    atomicAdd(&g_den[dst * 4 + h], ex);
}

// ---------------- k4: weighted scatter-sum of xl[src] ---------------------
__global__ void k4_scatter(const int* __restrict__ ei) {
    int e = (blockIdx.x * blockDim.x + threadIdx.x) >> 5;
    int lane = threadIdx.x & 31;
    if (e >= EE) return;
    int src = ei[e];
    int dst = ei[EE + e];
    int h = lane >> 3;
    float ex = g_logits[e * 4 + h];
    float den = g_den[dst * 4 + h];
    float alpha = ex / (den + 1e-16f);
    float4 v = ((const float4*)g_xl)[src * 32 + lane];
    v.x *= alpha; v.y *= alpha; v.z *= alpha; v.w *= alpha;
    float* p = g_accum + (size_t)dst * HID + lane * 4;
    asm volatile("red.global.add.v4.f32 [%0], {%1, %2, %3, %4};"
                 :: "l"(p), "f"(v.x), "f"(v.y), "f"(v.z), "f"(v.w)
                 : "memory");
}

// ---------------- k5: RMSNorm -> FFN(GELU, tf32 mma) -> RMSNorm -----------
__global__ void __launch_bounds__(256)
k5_mma(const float* __restrict__ x, const float* __restrict__ bias_gat,
       const float* __restrict__ wn1,
       const float* __restrict__ W1, const float* __restrict__ b1,
       const float* __restrict__ W2, const float* __restrict__ b2,
       const float* __restrict__ wn2, float* __restrict__ out) {
    extern __shared__ float sm[];
    float* hs = sm;                  // normed h, tf32, k-permuted
    float* wb = sm + 128 * SROW;     // W1 / W2 chunk, tf32, k-permuted
    float* gb = sm + 2 * 128 * SROW; // gelu output chunk / z buffer
    const float EPS = 1.1920929e-07f;
    const float IS2 = 0.70710678118654752f;
    int tid = threadIdx.x, warp = tid >> 5, lane = tid & 31;
    int wm = warp >> 2, wn = warp & 3;
    int lr = lane >> 2, lc2 = (lane & 3) << 1;
    int row0 = blockIdx.x * 128;

    // phase0: h = rmsnorm(x + accum + bias_gat, wn1) -> hs
    for (int r = 0; r < 16; r++) {
        int row = warp * 16 + r, node = row0 + row;
        float4 v = make_float4(0.f, 0.f, 0.f, 0.f);
        if (node < NN) {
            float4 xv = ((const float4*)x)[node * 32 + lane];
            float4 av = ((const float4*)g_accum)[node * 32 + lane];
            float4 bg = ((const float4*)bias_gat)[lane];
            v = make_float4(xv.x + av.x + bg.x, xv.y + av.y + bg.y,
                            xv.z + av.z + bg.z, xv.w + av.w + bg.w);
        }
        float ss = v.x * v.x + v.y * v.y + v.z * v.z + v.w * v.w;
#pragma unroll
        for (int o = 16; o > 0; o >>= 1) ss += __shfl_xor_sync(0xffffffffu, ss, o);
        float rs = rsqrtf(ss * (1.f / 128.f) + EPS);
        float4 w = ((const float4*)wn1)[lane];
        int c0 = lane * 4;
        hs[row * SROW + permk(c0)]     = tf32r(v.x * rs * w.x);
        hs[row * SROW + permk(c0 + 1)] = tf32r(v.y * rs * w.y);
        hs[row * SROW + permk(c0 + 2)] = tf32r(v.z * rs * w.z);
        hs[row * SROW + permk(c0 + 3)] = tf32r(v.w * rs * w.w);
    }

    float F[4][4][4];
#pragma unroll
    for (int i = 0; i < 4; i++)
#pragma unroll
        for (int j = 0; j < 4; j++)
#pragma unroll
            for (int e = 0; e < 4; e++) F[i][j][e] = 0.f;

    for (int ci = 0; ci < 4; ci++) {
        int n0 = ci * 128;
        __syncthreads();   // hs ready (ci=0) / prev GEMM2 reads of wb+gb done
        // stage W1[:, n0:n0+128] as [n][k] (tf32, permuted)
        for (int idx = tid; idx < 128 * 32; idx += 256) {
            int k = idx >> 5, n4 = (idx & 31) << 2;
            float4 w = *(const float4*)(W1 + k * 512 + n0 + n4);
            int kp = permk(k);
            wb[(n4 + 0) * SROW + kp] = tf32r(w.x);
            wb[(n4 + 1) * SROW + kp] = tf32r(w.y);
            wb[(n4 + 2) * SROW + kp] = tf32r(w.z);
            wb[(n4 + 3) * SROW + kp] = tf32r(w.w);
        }
        __syncthreads();

        // GEMM1: C1 = hs @ W1chunk
        float c1[4][4][4];
#pragma unroll
        for (int i = 0; i < 4; i++)
#pragma unroll
            for (int j = 0; j < 4; j++)
#pragma unroll
                for (int e = 0; e < 4; e++) c1[i][j][e] = 0.f;
        warp_gemm(hs + (wm * 64 + lr) * SROW + lc2,
                  wb + (wn * 32 + lr) * SROW + lc2, c1);

        // GELU -> gb (tf32, permuted)
#pragma unroll
        for (int nt = 0; nt < 4; nt++) {
            int colb = wn * 32 + nt * 8 + lc2;
            float bb0 = b1[n0 + colb], bb1 = b1[n0 + colb + 1];
#pragma unroll
            for (int mt = 0; mt < 4; mt++)
#pragma unroll
                for (int e = 0; e < 4; e++) {
                    float u = c1[mt][nt][e] + ((e & 1) ? bb1 : bb0);
                    float g = 0.5f * u * (1.f + erff(u * IS2));
                    int row = wm * 64 + mt * 16 + lr + ((e >> 1) << 3);
                    int col = colb + (e & 1);
                    gb[row * SROW + permk(col)] = tf32r(g);
                }
        }
        __syncthreads();   // gb ready, wb (W1) reads done

        // stage W2[n0:n0+128, :] transposed as [out][k] (tf32, permuted)
        for (int idx = tid; idx < 128 * 32; idx += 256) {
            int k = idx >> 5, o4 = (idx & 31) << 2;
            float4 w = *(const float4*)(W2 + (size_t)(n0 + k) * HID + o4);
            int kp = permk(k);
            wb[(o4 + 0) * SROW + kp] = tf32r(w.x);
            wb[(o4 + 1) * SROW + kp] = tf32r(w.y);
            wb[(o4 + 2) * SROW + kp] = tf32r(w.z);
            wb[(o4 + 3) * SROW + kp] = tf32r(w.w);
        }
        __syncthreads();

        // GEMM2: F += gb @ W2chunk
        warp_gemm(gb + (wm * 64 + lr) * SROW + lc2,
                  wb + (wn * 32 + lr) * SROW + lc2, F);
    }
    __syncthreads();

    // epilogue: z = h + F + b2 -> gb (plain layout)
#pragma unroll
    for (int nt = 0; nt < 4; nt++) {
        int col0 = wn * 32 + nt * 8 + lc2;
        float bb0 = b2[col0], bb1 = b2[col0 + 1];
#pragma unroll
        for (int mt = 0; mt < 4; mt++)
#pragma unroll
            for (int e = 0; e < 4; e++) {
                int row = wm * 64 + mt * 16 + lr + ((e >> 1) << 3);
                int col = col0 + (e & 1);
                float z = hs[row * SROW + permk(col)] + F[mt][nt][e]
                          + ((e & 1) ? bb1 : bb0);
                gb[row * SROW + col] = z;
            }
    }
    __syncthreads();

    // phase3: out = rmsnorm(z, wn2)
    for (int r = 0; r < 16; r++) {
        int row = warp * 16 + r, node = row0 + row;
        int c0 = lane * 4;
        float z0 = gb[row * SROW + c0];
        float z1 = gb[row * SROW + c0 + 1];
        float z2 = gb[row * SROW + c0 + 2];
        float z3 = gb[row * SROW + c0 + 3];
        float ss = z0 * z0 + z1 * z1 + z2 * z2 + z3 * z3;
#pragma unroll
        for (int o = 16; o > 0; o >>= 1) ss += __shfl_xor_sync(0xffffffffu, ss, o);
        float rs = rsqrtf(ss * (1.f / 128.f) + EPS);
        float4 w = ((const float4*)wn2)[lane];
        if (node < NN) {
            ((float4*)out)[node * 32 + lane] =
                make_float4(z0 * rs * w.x, z1 * rs * w.y,
                            z2 * rs * w.z, z3 * rs * w.w);
        }
    }
}

// ---------------- launch ---------------------------------------------------
extern "C" void kernel_launch(void* const* d_in, const int* in_sizes, int n_in,
                              void* d_out, int out_size) {
    const float* x        = (const float*)d_in[0];
    const int*   ei       = (const int*)  d_in[1];
    const float* ea       = (const float*)d_in[2];
    const float* Wl       = (const float*)d_in[3];
    const float* bl       = (const float*)d_in[4];
    const float* Wr       = (const float*)d_in[5];
    const float* br       = (const float*)d_in[6];
    const float* We       = (const float*)d_in[7];
    const float* att      = (const float*)d_in[8];
    const float* bias_gat = (const float*)d_in[9];
    const float* wn1      = (const float*)d_in[10];
    const float* wn2      = (const float*)d_in[11];
    const float* W1       = (const float*)d_in[12];
    const float* b1       = (const float*)d_in[13];
    const float* W2       = (const float*)d_in[14];
    const float* b2       = (const float*)d_in[15];
    float* out = (float*)d_out;

    const int SM1 = 2 * 128 * SROW * 4;   // 135168 B
    const int SM5 = 3 * 128 * SROW * 4;   // 202752 B
    cudaFuncSetAttribute(k1_mma, cudaFuncAttributeMaxDynamicSharedMemorySize, SM1);
    cudaFuncSetAttribute(k5_mma, cudaFuncAttributeMaxDynamicSharedMemorySize, SM5);

    const int NB = (NN + 127) / 128;      // 391

    k0_init<<<(NN * HID + 255) / 256, 256>>>();
    k1_mma<<<NB, 256, SM1>>>(x, Wl, bl, Wr, br);
    k2_logits<<<EE / 8, 256>>>(ei, ea, We, att);
    k3_softmax<<<(EE * 4) / 256, 256>>>(ei);
    k4_scatter<<<EE / 8, 256>>>(ei);
    k5_mma<<<NB, 256, SM5>>>(x, bias_gat, wn1, W1, b1, W2, b2, wn2, out);
}